// round 14
// baseline (speedup 1.0000x reference)
#include <cuda_runtime.h>
#include <cuda_fp16.h>
#include <math.h>
#include <stdint.h>

#define Bz   16
#define Tt   500
#define Cc   512
#define Kk   7
#define NHh  8
#define HD   64
#define HIDd 2048
#define Ll   3
#define NCb  2
#define BT   (Bz * Tt)
#define MT   8064
#define QKVS 1536
#define SCALE 0.125f

// ---------------- scratch (device globals) ----------------------------------
__device__ __half g_hA[MT * Cc];
__device__ __half g_hB[MT * Cc];
__device__ __half g_hH[MT * HIDd];
__device__ float  g_f[MT * Cc];
__device__ __half g_pwh[Ll * NCb * Cc * Cc];
__device__ __half g_qkvh[Ll * QKVS * Cc];
__device__ float  g_bqkv[Ll * QKVS];
__device__ __half g_woh[Ll * Cc * Cc];
__device__ __half g_w1h[Ll * HIDd * Cc];
__device__ __half g_w2h[Ll * Cc * HIDd];

// ---------------- helpers ---------------------------------------------------
__device__ __forceinline__ void mma_f16(float* c, const uint32_t* a, const uint32_t* b) {
    asm volatile(
        "mma.sync.aligned.m16n8k16.row.col.f32.f16.f16.f32 "
        "{%0,%1,%2,%3}, {%4,%5,%6,%7}, {%8,%9}, {%0,%1,%2,%3};"
        : "+f"(c[0]), "+f"(c[1]), "+f"(c[2]), "+f"(c[3])
        : "r"(a[0]), "r"(a[1]), "r"(a[2]), "r"(a[3]), "r"(b[0]), "r"(b[1]));
}
__device__ __forceinline__ void cpa16h(__half* dst, const __half* src) {
    unsigned d = (unsigned)__cvta_generic_to_shared(dst);
    asm volatile("cp.async.ca.shared.global [%0], [%1], 16;" :: "r"(d), "l"(src));
}
__device__ __forceinline__ void ldsm_x4(uint32_t* r, uint32_t addr) {
    asm volatile("ldmatrix.sync.aligned.m8n8.x4.shared.b16 {%0,%1,%2,%3}, [%4];"
        : "=r"(r[0]), "=r"(r[1]), "=r"(r[2]), "=r"(r[3]) : "r"(addr));
}
__device__ __forceinline__ void ldsm_x2(uint32_t* r, uint32_t addr) {
    asm volatile("ldmatrix.sync.aligned.m8n8.x2.shared.b16 {%0,%1}, [%2];"
        : "=r"(r[0]), "=r"(r[1]) : "r"(addr));
}

// ---------------- weight prep ------------------------------------------------
#define NPW   (Ll * NCb * Cc * Cc)
#define NQKV  (Ll * QKVS * Cc)
#define NO_   (Ll * Cc * Cc)
#define NW1   (Ll * HIDd * Cc)
#define NW2   (Ll * Cc * HIDd)
#define NQB_  (Ll * QKVS)
#define NPREP1 (NPW + NQKV + NO_ + NW1 + NW2)

__global__ void prep_weights(const float* __restrict__ pw_w,
                             const float* __restrict__ wq, const float* __restrict__ wk,
                             const float* __restrict__ wv,
                             const float* __restrict__ wo, const float* __restrict__ w1,
                             const float* __restrict__ w2) {
    int i = blockIdx.x * 256 + threadIdx.x;
    if (i >= NPREP1) return;
    if (i < NPW) { g_pwh[i] = __float2half(pw_w[i]); return; }
    i -= NPW;
    if (i < NQKV) {
        int c = i % Cc;
        int n = (i / Cc) % QKVS;
        int l = i / (Cc * QKVS);
        const float* src = (n < Cc) ? wq : (n < 2 * Cc) ? wk : wv;
        g_qkvh[i] = __float2half(src[(size_t)l * Cc * Cc + (size_t)(n & (Cc - 1)) * Cc + c]);
        return;
    }
    i -= NQKV;
    if (i < NO_) { g_woh[i] = __float2half(wo[i]); return; }
    i -= NO_;
    if (i < NW1) { g_w1h[i] = __float2half(w1[i]); return; }
    i -= NW1;
    g_w2h[i] = __float2half(w2[i]);
}

__global__ void prep_bias(const float* __restrict__ bq, const float* __restrict__ bk,
                          const float* __restrict__ bv) {
    int i = blockIdx.x * 256 + threadIdx.x;
    if (i >= NQB_) return;
    int n = i % QKVS;
    int l = i / QKVS;
    const float* src = (n < Cc) ? bq : (n < 2 * Cc) ? bk : bv;
    g_bqkv[i] = src[l * Cc + (n & (Cc - 1))];
}

// ---------------- depthwise conv: 2 channels/thread ------------------------
__device__ __forceinline__ float2 ld2(const float* p)  { return *(const float2*)p; }
__device__ __forceinline__ float2 ld2(const __half* p) { return __half22float2(*(const __half2*)p); }

template <typename Tin>
__global__ void dwconv_kernel(const Tin* __restrict__ x,
                              const float* __restrict__ w,
                              const float* __restrict__ bias,
                              __half* __restrict__ out) {
    int idx = blockIdx.x * 256 + threadIdx.x;
    if (idx >= BT * 256) return;
    int c  = (idx & 255) * 2;
    int bt = idx >> 8;
    int t  = bt % Tt;
    int b  = bt / Tt;
    float w0[Kk], w1[Kk];
#pragma unroll
    for (int k = 0; k < Kk; k++) { w0[k] = w[c * Kk + k]; w1[k] = w[(c + 1) * Kk + k]; }
    float a0 = bias[c], a1 = bias[c + 1];
#pragma unroll
    for (int k = 0; k < Kk; k++) {
        int tt = t + k - Kk / 2;
        if (tt >= 0 && tt < Tt) {
            float2 xv = ld2(x + ((size_t)(b * Tt + tt) << 9) + c);
            a0 = fmaf(xv.x, w0[k], a0);
            a1 = fmaf(xv.y, w1[k], a1);
        }
    }
    *(__half2*)&out[((size_t)bt << 9) + c] = __floats2half2_rn(a0, a1);
}

// ---------------- FP16 GEMM: 128x256 tile, 512 thr, 4-stage, ldmatrix ------
#define GBM 128
#define GBN 256
#define BK  32
#define HSTRIDE 40
#define NSTAGE 4
#define A_STH (GBM * HSTRIDE)                   /* 5120 halfs */
#define B_STH (GBN * HSTRIDE)                   /* 10240 halfs */
#define SMEM_GEMM (NSTAGE * (A_STH + B_STH) * 2)   /* 122880 bytes */

template <int RELU, int HOUT>
__global__ void __launch_bounds__(512)
gemm_f16(const __half* __restrict__ A, const __half* __restrict__ W,
         const float* __restrict__ bias, void* __restrict__ Cout,
         int N_, int Kd) {
    extern __shared__ __half hsm[];
    __half* Asm = hsm;
    __half* Bsm = hsm + NSTAGE * A_STH;

    int tid  = threadIdx.x;
    int lane = tid & 31;
    int wid  = tid >> 5;           // 0..15
    int g = lane >> 2;
    int t = lane & 3;
    int warpM = wid >> 3;          // 0..1  (64 rows each)
    int warpN = wid & 7;           // 0..7  (32 cols each)
    int rowBase = blockIdx.y * GBM;
    int colBase = blockIdx.x * GBN;

    const __half* Abase = A + (size_t)rowBase * Kd;
    const __half* Wbase = W + (size_t)colBase * Kd;

    // loader: A 512 quads (1/thread), B 1024 quads (2/thread)
    int ar = tid >> 2,  aq = (tid & 3) * 8;
    int b0i = tid,        br0 = b0i >> 2, bq0 = (b0i & 3) * 8;
    int b1i = tid + 512,  br1 = b1i >> 2, bq1 = (b1i & 3) * 8;

    // ldmatrix lane addressing (proven R13)
    uint32_t aBase = (uint32_t)__cvta_generic_to_shared(Asm);
    uint32_t bBase = (uint32_t)__cvta_generic_to_shared(Bsm);
    int rowA = lane & 15;
    int colA = (lane >> 4) << 4;
    int rowB = lane & 7;
    int colB = (lane & 8) ? 16 : 0;
    uint32_t aoff[4], boff[4];
#pragma unroll
    for (int i = 0; i < 4; i++)
        aoff[i] = (uint32_t)((warpM * 64 + i * 16 + rowA) * (HSTRIDE * 2) + colA);
#pragma unroll
    for (int j = 0; j < 4; j++)
        boff[j] = (uint32_t)((warpN * 32 + j * 8 + rowB) * (HSTRIDE * 2) + colB);

    float acc[4][4][4];
#pragma unroll
    for (int i = 0; i < 4; i++)
#pragma unroll
        for (int j = 0; j < 4; j++)
#pragma unroll
            for (int r = 0; r < 4; r++) acc[i][j][r] = 0.f;

    int KT = Kd / BK;

    auto load_stage = [&](int kt, int s) {
        int k0 = kt * BK;
        __half* as = Asm + s * A_STH;
        __half* bs = Bsm + s * B_STH;
        cpa16h(&as[ar * HSTRIDE + aq],   Abase + (size_t)ar * Kd + k0 + aq);
        cpa16h(&bs[br0 * HSTRIDE + bq0], Wbase + (size_t)br0 * Kd + k0 + bq0);
        cpa16h(&bs[br1 * HSTRIDE + bq1], Wbase + (size_t)br1 * Kd + k0 + bq1);
        asm volatile("cp.async.commit_group;");
    };

    load_stage(0, 0);
    load_stage(1, 1);
    load_stage(2, 2);

    for (int kt = 0; kt < KT; kt++) {
        int s = kt % NSTAGE;
        asm volatile("cp.async.wait_group %0;" :: "n"(NSTAGE - 2));
        __syncthreads();
        if (kt + NSTAGE - 1 < KT) load_stage(kt + NSTAGE - 1, (kt + NSTAGE - 1) % NSTAGE);
        else asm volatile("cp.async.commit_group;");

        uint32_t aS = aBase + s * (A_STH * 2);
        uint32_t bS = bBase + s * (B_STH * 2);
#pragma unroll
        for (int ks = 0; ks < 2; ks++) {
            int kb = ks * 32;
            uint32_t af[4][4], bf[4][2];
#pragma unroll
            for (int i = 0; i < 4; i++) ldsm_x4(af[i], aS + aoff[i] + kb);
#pragma unroll
            for (int j = 0; j < 4; j++) ldsm_x2(bf[j], bS + boff[j] + kb);
#pragma unroll
            for (int i = 0; i < 4; i++)
#pragma unroll
                for (int j = 0; j < 4; j++)
                    mma_f16(acc[i][j], af[i], bf[j]);
        }
    }

#pragma unroll
    for (int i = 0; i < 4; i++) {
        int m0 = rowBase + warpM * 64 + i * 16 + g;
#pragma unroll
        for (int j = 0; j < 4; j++) {
            int n = colBase + warpN * 32 + j * 8 + 2 * t;
            float b0 = bias[n], b1 = bias[n + 1];
            float v0 = acc[i][j][0] + b0;
            float v1 = acc[i][j][1] + b1;
            float v2 = acc[i][j][2] + b0;
            float v3 = acc[i][j][3] + b1;
            if (RELU) {
                v0 = fmaxf(v0, 0.f); v1 = fmaxf(v1, 0.f);
                v2 = fmaxf(v2, 0.f); v3 = fmaxf(v3, 0.f);
            }
            if (HOUT) {
                __half* Ch = (__half*)Cout;
                *(__half2*)&Ch[(size_t)m0 * N_ + n]       = __floats2half2_rn(v0, v1);
                *(__half2*)&Ch[(size_t)(m0 + 8) * N_ + n] = __floats2half2_rn(v2, v3);
            } else {
                float* Cf = (float*)Cout;
                *(float2*)&Cf[(size_t)m0 * N_ + n]       = make_float2(v0, v1);
                *(float2*)&Cf[(size_t)(m0 + 8) * N_ + n] = make_float2(v2, v3);
            }
        }
    }
}

// ---------------- LayerNorm: float4 + shfl ----------------------------------
template <int FINAL>
__global__ void ln_kernel(const float* __restrict__ x,
                          const float* __restrict__ g,
                          const float* __restrict__ be,
                          __half* __restrict__ outh,
                          float* __restrict__ outf) {
    int row = blockIdx.x;
    int tid = threadIdx.x;   // 128
    int lane = tid & 31, wrp = tid >> 5;
    float4 v = ((const float4*)(x + (size_t)row * Cc))[tid];

    __shared__ float ws[4];
    __shared__ float bc[2];

    float s = v.x + v.y + v.z + v.w;
#pragma unroll
    for (int o = 16; o > 0; o >>= 1) s += __shfl_xor_sync(0xffffffffu, s, o);
    if (lane == 0) ws[wrp] = s;
    __syncthreads();
    if (tid == 0) bc[0] = (ws[0] + ws[1] + ws[2] + ws[3]) * (1.f / Cc);
    __syncthreads();
    float mean = bc[0];

    float dx = v.x - mean, dy = v.y - mean, dz = v.z - mean, dw = v.w - mean;
    float vs = dx * dx + dy * dy + dz * dz + dw * dw;
#pragma unroll
    for (int o = 16; o > 0; o >>= 1) vs += __shfl_xor_sync(0xffffffffu, vs, o);
    if (lane == 0) ws[wrp] = vs;
    __syncthreads();
    if (tid == 0) bc[1] = rsqrtf((ws[0] + ws[1] + ws[2] + ws[3]) * (1.f / Cc) + 1e-5f);
    __syncthreads();
    float inv = bc[1];

    float4 gv = ((const float4*)g)[tid];
    float4 bv = ((const float4*)be)[tid];
    float o0 = dx * inv * gv.x + bv.x;
    float o1 = dy * inv * gv.y + bv.y;
    float o2 = dz * inv * gv.z + bv.z;
    float o3 = dw * inv * gv.w + bv.w;
    if (FINAL) {
        ((float4*)(outf + (size_t)row * Cc))[tid] = make_float4(o0, o1, o2, o3);
    } else {
        __half* dst = outh + (size_t)row * Cc + tid * 4;
        *(__half2*)dst       = __floats2half2_rn(o0, o1);
        *(__half2*)(dst + 2) = __floats2half2_rn(o2, o3);
    }
}

// ---------------- attention: tensor-core (mma.sync), proven R12 ------------
#define AQB 32
#define AJT 64
#define ATH 256
#define QSTW 36
#define KSTW 36
#define SCST 516
#define PSTW 260
#define SM_Q   0
#define SM_K   4608
#define SM_SC  13824
#define SM_P   79872
#define SM_INV 113152
#define SMEM_ATTN 113280

__global__ void __launch_bounds__(ATH)
attn_kernel(const __half* __restrict__ QKV, __half* __restrict__ O) {
    extern __shared__ char asmem[];
    uint32_t* qsm  = (uint32_t*)(asmem + SM_Q);
    uint32_t* ksm  = (uint32_t*)(asmem + SM_K);
    float*    sc   = (float*)(asmem + SM_SC);
    uint32_t* psm  = (uint32_t*)(asmem + SM_P);
    __half*   psmh = (__half*)psm;
    float*    invs = (float*)(asmem + SM_INV);

    int qt0 = blockIdx.x * AQB;
    int h   = blockIdx.y;
    int b   = blockIdx.z;
    int tid = threadIdx.x;
    int lane = tid & 31, wid = tid >> 5;
    int g = lane >> 2, t = lane & 3;
    int n0 = wid * 8;

    for (int i = tid; i < AQB * PSTW; i += ATH) psm[i] = 0;

    for (int i = tid; i < AQB * 16; i += ATH) {
        int r = i >> 4, dp = i & 15;
        int qq = qt0 + r;
        uint2 u = make_uint2(0u, 0u);
        if (qq < Tt) u = *(const uint2*)&QKV[(size_t)(b * Tt + qq) * QKVS + h * HD + dp * 4];
        qsm[r * QSTW + dp * 2]     = u.x;
        qsm[r * QSTW + dp * 2 + 1] = u.y;
    }
    __syncthreads();

    int qmax = min(qt0 + AQB - 1, Tt - 1);
    int ntiles = qmax / AJT + 1;

    for (int jt = 0; jt < ntiles; jt++) {
        int j0 = jt * AJT;
        for (int i = tid; i < AJT * 16; i += ATH) {
            int r = i >> 4, dp = i & 15;
            int j = j0 + r;
            uint2 u = make_uint2(0u, 0u);
            if (j < Tt) u = *(const uint2*)&QKV[(size_t)(b * Tt + j) * QKVS + Cc + h * HD + dp * 4];
            ksm[r * KSTW + dp * 2]     = u.x;
            ksm[r * KSTW + dp * 2 + 1] = u.y;
        }
        __syncthreads();

        float acc[2][4];
#pragma unroll
        for (int i = 0; i < 2; i++)
#pragma unroll
            for (int r = 0; r < 4; r++) acc[i][r] = 0.f;

#pragma unroll
        for (int ks = 0; ks < 4; ks++) {
            int kc = ks * 8;
            uint32_t bfr[2];
            bfr[0] = ksm[(n0 + g) * KSTW + kc + t];
            bfr[1] = ksm[(n0 + g) * KSTW + kc + t + 4];
#pragma unroll
            for (int i = 0; i < 2; i++) {
                int r = i * 16;
                uint32_t af[4];
                af[0] = qsm[(r + g) * QSTW + kc + t];
                af[1] = qsm[(r + g + 8) * QSTW + kc + t];
                af[2] = qsm[(r + g) * QSTW + kc + t + 4];
                af[3] = qsm[(r + g + 8) * QSTW + kc + t + 4];
                mma_f16(acc[i], af, bfr);
            }
        }
        int col = j0 + n0 + 2 * t;
#pragma unroll
        for (int i = 0; i < 2; i++) {
            int m = i * 16 + g;
            int qa = qt0 + m;
            int qb = qa + 8;
            float s0 = (col     <= qa) ? acc[i][0] * SCALE : -1e30f;
            float s1 = (col + 1 <= qa) ? acc[i][1] * SCALE : -1e30f;
            float s2 = (col     <= qb) ? acc[i][2] * SCALE : -1e30f;
            float s3 = (col + 1 <= qb) ? acc[i][3] * SCALE : -1e30f;
            *(float2*)&sc[m * SCST + col]       = make_float2(s0, s1);
            *(float2*)&sc[(m + 8) * SCST + col] = make_float2(s2, s3);
        }
        __syncthreads();
    }

    for (int rr = 0; rr < 4; rr++) {
        int m = wid * 4 + rr;
        int q = qt0 + m;
        if (q > qmax) continue;
        float* srow = sc + m * SCST;
        float mx = -1e30f;
        for (int j = lane; j <= q; j += 32) mx = fmaxf(mx, srow[j]);
#pragma unroll
        for (int o = 16; o > 0; o >>= 1) mx = fmaxf(mx, __shfl_xor_sync(0xffffffffu, mx, o));
        float sum = 0.f;
        for (int j = lane; j <= q; j += 32) {
            float e = __expf(srow[j] - mx);
            psmh[m * (PSTW * 2) + j] = __float2half(e);
            sum += e;
        }
#pragma unroll
        for (int o = 16; o > 0; o >>= 1) sum += __shfl_xor_sync(0xffffffffu, sum, o);
        if (lane == 0) invs[m] = 1.f / sum;
    }
    __syncthreads();

    float oacc[2][4];
#pragma unroll
    for (int i = 0; i < 2; i++)
#pragma unroll
        for (int r = 0; r < 4; r++) oacc[i][r] = 0.f;

    for (int jt = 0; jt < ntiles; jt++) {
        int j0 = jt * AJT;
        for (int i = tid; i < AJT * 16; i += ATH) {
            int r  = i >> 4;
            int dp = (i & 15) * 4;
            int j  = j0 + r;
            uint2 u = make_uint2(0u, 0u);
            if (j < Tt) u = *(const uint2*)&QKV[(size_t)(b * Tt + j) * QKVS + 2 * Cc + h * HD + dp];
            __half hs[4];
            *(uint2*)hs = u;
            __half* vt = (__half*)ksm;
            vt[(dp + 0) * (KSTW * 2) + r] = hs[0];
            vt[(dp + 1) * (KSTW * 2) + r] = hs[1];
            vt[(dp + 2) * (KSTW * 2) + r] = hs[2];
            vt[(dp + 3) * (KSTW * 2) + r] = hs[3];
        }
        __syncthreads();

        int pw = (j0 >> 1);
#pragma unroll
        for (int ks = 0; ks < 4; ks++) {
            int kc = ks * 8;
            uint32_t bfr[2];
            bfr[0] = ksm[(n0 + g) * KSTW + kc + t];
            bfr[1] = ksm[(n0 + g) * KSTW + kc + t + 4];
#pragma unroll
            for (int i = 0; i < 2; i++) {
                int r = i * 16;
                uint32_t af[4];
                af[0] = psm[(r + g) * PSTW + pw + kc + t];
                af[1] = psm[(r + g + 8) * PSTW + pw + kc + t];
                af[2] = psm[(r + g) * PSTW + pw + kc + t + 4];
                af[3] = psm[(r + g + 8) * PSTW + pw + kc + t + 4];
                mma_f16(oacc[i], af, bfr);
            }
        }
        __syncthreads();
    }

#pragma unroll
    for (int i = 0; i < 2; i++) {
        int m = i * 16 + g;
        int qa = qt0 + m;
        if (qa < Tt) {
            float iv = invs[m];
            *(__half2*)&O[(size_t)(b * Tt + qa) * Cc + h * HD + n0 + 2 * t] =
                __floats2half2_rn(oacc[i][0] * iv, oacc[i][1] * iv);
        }
        int qb = qa + 8;
        if (qb < Tt) {
            float iv = invs[m + 8];
            *(__half2*)&O[(size_t)(b * Tt + qb) * Cc + h * HD + n0 + 2 * t] =
                __floats2half2_rn(oacc[i][2] * iv, oacc[i][3] * iv);
        }
    }
}

// ---------------- host orchestration ---------------------------------------
extern "C" void kernel_launch(void* const* d_in, const int* in_sizes, int n_in,
                              void* d_out, int out_size) {
    (void)in_sizes; (void)n_in; (void)out_size;
    const float* x     = (const float*)d_in[0];
    const float* dw_w  = (const float*)d_in[1];
    const float* dw_b  = (const float*)d_in[2];
    const float* pw_w  = (const float*)d_in[3];
    const float* pw_b  = (const float*)d_in[4];
    const float* cln_g = (const float*)d_in[5];
    const float* cln_b = (const float*)d_in[6];
    const float* wq    = (const float*)d_in[7];
    const float* bq    = (const float*)d_in[8];
    const float* wk    = (const float*)d_in[9];
    const float* bk    = (const float*)d_in[10];
    const float* wv    = (const float*)d_in[11];
    const float* bv    = (const float*)d_in[12];
    const float* wo    = (const float*)d_in[13];
    const float* bo    = (const float*)d_in[14];
    const float* aln_g = (const float*)d_in[15];
    const float* aln_b = (const float*)d_in[16];
    const float* w1    = (const float*)d_in[17];
    const float* b1    = (const float*)d_in[18];
    const float* w2    = (const float*)d_in[19];
    const float* b2    = (const float*)d_in[20];
    const float* fln_g = (const float*)d_in[21];
    const float* fln_b = (const float*)d_in[22];
    float* out = (float*)d_out;

    __half *hA, *hB, *hH, *pwh, *qkvh, *woh, *w1h, *w2h;
    float *f32buf, *bqkv;
    cudaGetSymbolAddress((void**)&hA,   g_hA);
    cudaGetSymbolAddress((void**)&hB,   g_hB);
    cudaGetSymbolAddress((void**)&hH,   g_hH);
    cudaGetSymbolAddress((void**)&f32buf, g_f);
    cudaGetSymbolAddress((void**)&pwh,  g_pwh);
    cudaGetSymbolAddress((void**)&qkvh, g_qkvh);
    cudaGetSymbolAddress((void**)&bqkv, g_bqkv);
    cudaGetSymbolAddress((void**)&woh,  g_woh);
    cudaGetSymbolAddress((void**)&w1h,  g_w1h);
    cudaGetSymbolAddress((void**)&w2h,  g_w2h);

    cudaFuncSetAttribute(gemm_f16<0, 0>, cudaFuncAttributeMaxDynamicSharedMemorySize, SMEM_GEMM);
    cudaFuncSetAttribute(gemm_f16<0, 1>, cudaFuncAttributeMaxDynamicSharedMemorySize, SMEM_GEMM);
    cudaFuncSetAttribute(gemm_f16<1, 1>, cudaFuncAttributeMaxDynamicSharedMemorySize, SMEM_GEMM);
    cudaFuncSetAttribute(attn_kernel, cudaFuncAttributeMaxDynamicSharedMemorySize, SMEM_ATTN);

    dim3 gN512(Cc / GBN, MT / GBM);      // (2, 63)
    dim3 gN1536(QKVS / GBN, MT / GBM);   // (6, 63)
    dim3 gN2048(HIDd / GBN, MT / GBM);   // (8, 63)
    dim3 attnGrid((Tt + AQB - 1) / AQB, NHh, Bz);
    int dwBlocks = BT;

    prep_weights<<<(NPREP1 + 255) / 256, 256>>>(pw_w, wq, wk, wv, wo, w1, w2);
    prep_bias<<<(NQB_ + 255) / 256, 256>>>(bq, bk, bv);

    const float* cur = x;
    for (int l = 0; l < Ll; l++) {
        // ---- conv block 0 ----
        dwconv_kernel<float><<<dwBlocks, 256>>>(cur,
            dw_w + (size_t)(l * NCb + 0) * Cc * Kk, dw_b + (size_t)(l * NCb + 0) * Cc, hA);
        gemm_f16<0, 0><<<gN512, 512, SMEM_GEMM>>>(hA, pwh + (size_t)(l * NCb + 0) * Cc * Cc,
            pw_b + (size_t)(l * NCb + 0) * Cc, f32buf, Cc, Cc);
        ln_kernel<0><<<BT, 128>>>(f32buf, cln_g + (size_t)(l * NCb + 0) * Cc,
            cln_b + (size_t)(l * NCb + 0) * Cc, hB, nullptr);

        // ---- conv block 1 ----
        dwconv_kernel<__half><<<dwBlocks, 256>>>(hB,
            dw_w + (size_t)(l * NCb + 1) * Cc * Kk, dw_b + (size_t)(l * NCb + 1) * Cc, hA);
        gemm_f16<0, 0><<<gN512, 512, SMEM_GEMM>>>(hA, pwh + (size_t)(l * NCb + 1) * Cc * Cc,
            pw_b + (size_t)(l * NCb + 1) * Cc, f32buf, Cc, Cc);
        ln_kernel<0><<<BT, 128>>>(f32buf, cln_g + (size_t)(l * NCb + 1) * Cc,
            cln_b + (size_t)(l * NCb + 1) * Cc, hB, nullptr);

        // ---- attention ----
        gemm_f16<0, 1><<<gN1536, 512, SMEM_GEMM>>>(hB, qkvh + (size_t)l * QKVS * Cc,
            bqkv + (size_t)l * QKVS, hH, QKVS, Cc);
        attn_kernel<<<attnGrid, ATH, SMEM_ATTN>>>(hH, hA);
        gemm_f16<0, 0><<<gN512, 512, SMEM_GEMM>>>(hA, woh + (size_t)l * Cc * Cc,
            bo + (size_t)l * Cc, f32buf, Cc, Cc);
        ln_kernel<0><<<BT, 128>>>(f32buf, aln_g + (size_t)l * Cc, aln_b + (size_t)l * Cc, hB, nullptr);

        // ---- FFN ----
        gemm_f16<1, 1><<<gN2048, 512, SMEM_GEMM>>>(hB, w1h + (size_t)l * HIDd * Cc,
            b1 + (size_t)l * HIDd, hH, HIDd, Cc);
        gemm_f16<0, 0><<<gN512, 512, SMEM_GEMM>>>(hH, w2h + (size_t)l * Cc * HIDd,
            b2 + (size_t)l * Cc, f32buf, Cc, HIDd);

        float* Y = out + (size_t)l * BT * Cc;
        ln_kernel<1><<<BT, 128>>>(f32buf, fln_g + (size_t)l * Cc, fln_b + (size_t)l * Cc, nullptr, Y);
        cur = Y;
    }
}

// round 15
// speedup vs baseline: 1.0972x; 1.0972x over previous
#include <cuda_runtime.h>
#include <cuda_fp16.h>
#include <math.h>
#include <stdint.h>

#define Bz   16
#define Tt   500
#define Cc   512
#define Kk   7
#define NHh  8
#define HD   64
#define HIDd 2048
#define Ll   3
#define NCb  2
#define BT   (Bz * Tt)
#define MT   8064
#define QKVS 1536
#define SCALE 0.125f

// ---------------- scratch (device globals) ----------------------------------
__device__ __half g_hA[MT * Cc];
__device__ __half g_hB[MT * Cc];
__device__ __half g_hH[MT * HIDd];
__device__ float  g_f[MT * Cc];
__device__ __half g_pwh[Ll * NCb * Cc * Cc];
__device__ __half g_qkvh[Ll * QKVS * Cc];
__device__ float  g_bqkv[Ll * QKVS];
__device__ __half g_woh[Ll * Cc * Cc];
__device__ __half g_w1h[Ll * HIDd * Cc];
__device__ __half g_w2h[Ll * Cc * HIDd];

// ---------------- helpers ---------------------------------------------------
__device__ __forceinline__ void mma_f16(float* c, const uint32_t* a, const uint32_t* b) {
    asm volatile(
        "mma.sync.aligned.m16n8k16.row.col.f32.f16.f16.f32 "
        "{%0,%1,%2,%3}, {%4,%5,%6,%7}, {%8,%9}, {%0,%1,%2,%3};"
        : "+f"(c[0]), "+f"(c[1]), "+f"(c[2]), "+f"(c[3])
        : "r"(a[0]), "r"(a[1]), "r"(a[2]), "r"(a[3]), "r"(b[0]), "r"(b[1]));
}
__device__ __forceinline__ void cpa16h(__half* dst, const __half* src) {
    unsigned d = (unsigned)__cvta_generic_to_shared(dst);
    asm volatile("cp.async.ca.shared.global [%0], [%1], 16;" :: "r"(d), "l"(src));
}
__device__ __forceinline__ void ldsm_x4(uint32_t* r, uint32_t addr) {
    asm volatile("ldmatrix.sync.aligned.m8n8.x4.shared.b16 {%0,%1,%2,%3}, [%4];"
        : "=r"(r[0]), "=r"(r[1]), "=r"(r[2]), "=r"(r[3]) : "r"(addr));
}
__device__ __forceinline__ void ldsm_x2(uint32_t* r, uint32_t addr) {
    asm volatile("ldmatrix.sync.aligned.m8n8.x2.shared.b16 {%0,%1}, [%2];"
        : "=r"(r[0]), "=r"(r[1]) : "r"(addr));
}

// ---------------- weight prep ------------------------------------------------
#define NPW   (Ll * NCb * Cc * Cc)
#define NQKV  (Ll * QKVS * Cc)
#define NO_   (Ll * Cc * Cc)
#define NW1   (Ll * HIDd * Cc)
#define NW2   (Ll * Cc * HIDd)
#define NQB_  (Ll * QKVS)
#define NPREP1 (NPW + NQKV + NO_ + NW1 + NW2)

__global__ void prep_weights(const float* __restrict__ pw_w,
                             const float* __restrict__ wq, const float* __restrict__ wk,
                             const float* __restrict__ wv,
                             const float* __restrict__ wo, const float* __restrict__ w1,
                             const float* __restrict__ w2) {
    int i = blockIdx.x * 256 + threadIdx.x;
    if (i >= NPREP1) return;
    if (i < NPW) { g_pwh[i] = __float2half(pw_w[i]); return; }
    i -= NPW;
    if (i < NQKV) {
        int c = i % Cc;
        int n = (i / Cc) % QKVS;
        int l = i / (Cc * QKVS);
        const float* src = (n < Cc) ? wq : (n < 2 * Cc) ? wk : wv;
        g_qkvh[i] = __float2half(src[(size_t)l * Cc * Cc + (size_t)(n & (Cc - 1)) * Cc + c]);
        return;
    }
    i -= NQKV;
    if (i < NO_) { g_woh[i] = __float2half(wo[i]); return; }
    i -= NO_;
    if (i < NW1) { g_w1h[i] = __float2half(w1[i]); return; }
    i -= NW1;
    g_w2h[i] = __float2half(w2[i]);
}

__global__ void prep_bias(const float* __restrict__ bq, const float* __restrict__ bk,
                          const float* __restrict__ bv) {
    int i = blockIdx.x * 256 + threadIdx.x;
    if (i >= NQB_) return;
    int n = i % QKVS;
    int l = i / QKVS;
    const float* src = (n < Cc) ? bq : (n < 2 * Cc) ? bk : bv;
    g_bqkv[i] = src[l * Cc + (n & (Cc - 1))];
}

// ---------------- depthwise conv: sliding window, 4 t-outputs/thread -------
__device__ __forceinline__ float2 ld2(const float* p)  { return *(const float2*)p; }
__device__ __forceinline__ float2 ld2(const __half* p) { return __half22float2(*(const __half2*)p); }

template <typename Tin>
__global__ void dwconv_kernel(const Tin* __restrict__ x,
                              const float* __restrict__ w,
                              const float* __restrict__ bias,
                              __half* __restrict__ out) {
    int idx = blockIdx.x * 256 + threadIdx.x;      // over (BT/4)*256
    if (idx >= (BT / 4) * 256) return;
    int c   = (idx & 255) * 2;
    int bt4 = idx >> 8;
    int b   = bt4 / (Tt / 4);
    int t0  = (bt4 % (Tt / 4)) * 4;

    float w0[Kk], w1[Kk];
#pragma unroll
    for (int k = 0; k < Kk; k++) { w0[k] = w[c * Kk + k]; w1[k] = w[(c + 1) * Kk + k]; }
    float b0 = bias[c], b1 = bias[c + 1];
    float a0[4] = {b0, b0, b0, b0};
    float a1[4] = {b1, b1, b1, b1};

#pragma unroll
    for (int j = 0; j < 10; j++) {                 // window t0-3 .. t0+6
        int tt = t0 + j - 3;
        if (tt >= 0 && tt < Tt) {
            float2 xv = ld2(x + ((size_t)(b * Tt + tt) << 9) + c);
#pragma unroll
            for (int o = 0; o < 4; o++) {
                int k = j - o;
                if (k >= 0 && k < Kk) {
                    a0[o] = fmaf(xv.x, w0[k], a0[o]);
                    a1[o] = fmaf(xv.y, w1[k], a1[o]);
                }
            }
        }
    }
#pragma unroll
    for (int o = 0; o < 4; o++)
        *(__half2*)&out[((size_t)(b * Tt + t0 + o) << 9) + c] = __floats2half2_rn(a0[o], a1[o]);
}

// ---------------- FP16 GEMM: 128x256, 512 thr, BK=64, 3-stage, ldmatrix ----
#define GBM 128
#define GBN 256
#define BK  64
#define HSTRIDE 72                               /* halfs/row: 36 words, conflict-free */
#define NSTAGE 3
#define A_STH (GBM * HSTRIDE)                    /* 9216 halfs  (18432 B) */
#define B_STH (GBN * HSTRIDE)                    /* 18432 halfs (36864 B) */
#define SMEM_GEMM (NSTAGE * (A_STH + B_STH) * 2) /* 165888 bytes */

template <int RELU, int HOUT>
__global__ void __launch_bounds__(512)
gemm_f16(const __half* __restrict__ A, const __half* __restrict__ W,
         const float* __restrict__ bias, void* __restrict__ Cout,
         int N_, int Kd) {
    extern __shared__ __half hsm[];
    __half* Asm = hsm;
    __half* Bsm = hsm + NSTAGE * A_STH;

    int tid  = threadIdx.x;
    int lane = tid & 31;
    int wid  = tid >> 5;           // 0..15
    int g = lane >> 2;
    int t = lane & 3;
    int warpM = wid >> 3;          // 0..1  (64 rows)
    int warpN = wid & 7;           // 0..7  (32 cols)
    int rowBase = blockIdx.y * GBM;
    int colBase = blockIdx.x * GBN;

    const __half* Abase = A + (size_t)rowBase * Kd;
    const __half* Wbase = W + (size_t)colBase * Kd;

    // loader quads: A 1024 (2/thread), B 2048 (4/thread); row = qi>>3, q=(qi&7)*8
    int a0i = tid,        aR0 = a0i >> 3, aQ0 = (a0i & 7) * 8;
    int a1i = tid + 512,  aR1 = a1i >> 3, aQ1 = (a1i & 7) * 8;
    int bR[4], bQ[4];
#pragma unroll
    for (int k = 0; k < 4; k++) {
        int qi = tid + k * 512;
        bR[k] = qi >> 3;
        bQ[k] = (qi & 7) * 8;
    }

    // ldmatrix lane addressing (proven)
    uint32_t aBase = (uint32_t)__cvta_generic_to_shared(Asm);
    uint32_t bBase = (uint32_t)__cvta_generic_to_shared(Bsm);
    int rowA = lane & 15;
    int colA = (lane >> 4) << 4;
    int rowB = lane & 7;
    int colB = (lane & 8) ? 16 : 0;
    uint32_t aoff[4], boff[4];
#pragma unroll
    for (int i = 0; i < 4; i++)
        aoff[i] = (uint32_t)((warpM * 64 + i * 16 + rowA) * (HSTRIDE * 2) + colA);
#pragma unroll
    for (int j = 0; j < 4; j++)
        boff[j] = (uint32_t)((warpN * 32 + j * 8 + rowB) * (HSTRIDE * 2) + colB);

    float acc[4][4][4];
#pragma unroll
    for (int i = 0; i < 4; i++)
#pragma unroll
        for (int j = 0; j < 4; j++)
#pragma unroll
            for (int r = 0; r < 4; r++) acc[i][j][r] = 0.f;

    int KT = Kd / BK;

    auto load_stage = [&](int kt, int s) {
        int k0 = kt * BK;
        __half* as = Asm + s * A_STH;
        __half* bs = Bsm + s * B_STH;
        cpa16h(&as[aR0 * HSTRIDE + aQ0], Abase + (size_t)aR0 * Kd + k0 + aQ0);
        cpa16h(&as[aR1 * HSTRIDE + aQ1], Abase + (size_t)aR1 * Kd + k0 + aQ1);
#pragma unroll
        for (int k = 0; k < 4; k++)
            cpa16h(&bs[bR[k] * HSTRIDE + bQ[k]], Wbase + (size_t)bR[k] * Kd + k0 + bQ[k]);
        asm volatile("cp.async.commit_group;");
    };

    load_stage(0, 0);
    load_stage(1, 1);

    for (int kt = 0; kt < KT; kt++) {
        int s = kt % NSTAGE;
        asm volatile("cp.async.wait_group 1;");
        __syncthreads();
        if (kt + 2 < KT) load_stage(kt + 2, (kt + 2) % NSTAGE);
        else asm volatile("cp.async.commit_group;");

        uint32_t aS = aBase + s * (A_STH * 2);
        uint32_t bS = bBase + s * (B_STH * 2);
#pragma unroll
        for (int ks = 0; ks < 4; ks++) {
            int kb = ks * 32;
            uint32_t af[4][4], bf[4][2];
#pragma unroll
            for (int i = 0; i < 4; i++) ldsm_x4(af[i], aS + aoff[i] + kb);
#pragma unroll
            for (int j = 0; j < 4; j++) ldsm_x2(bf[j], bS + boff[j] + kb);
#pragma unroll
            for (int i = 0; i < 4; i++)
#pragma unroll
                for (int j = 0; j < 4; j++)
                    mma_f16(acc[i][j], af[i], bf[j]);
        }
    }

#pragma unroll
    for (int i = 0; i < 4; i++) {
        int m0 = rowBase + warpM * 64 + i * 16 + g;
#pragma unroll
        for (int j = 0; j < 4; j++) {
            int n = colBase + warpN * 32 + j * 8 + 2 * t;
            float b0 = bias[n], b1 = bias[n + 1];
            float v0 = acc[i][j][0] + b0;
            float v1 = acc[i][j][1] + b1;
            float v2 = acc[i][j][2] + b0;
            float v3 = acc[i][j][3] + b1;
            if (RELU) {
                v0 = fmaxf(v0, 0.f); v1 = fmaxf(v1, 0.f);
                v2 = fmaxf(v2, 0.f); v3 = fmaxf(v3, 0.f);
            }
            if (HOUT) {
                __half* Ch = (__half*)Cout;
                *(__half2*)&Ch[(size_t)m0 * N_ + n]       = __floats2half2_rn(v0, v1);
                *(__half2*)&Ch[(size_t)(m0 + 8) * N_ + n] = __floats2half2_rn(v2, v3);
            } else {
                float* Cf = (float*)Cout;
                *(float2*)&Cf[(size_t)m0 * N_ + n]       = make_float2(v0, v1);
                *(float2*)&Cf[(size_t)(m0 + 8) * N_ + n] = make_float2(v2, v3);
            }
        }
    }
}

// ---------------- LayerNorm: float4 + shfl ----------------------------------
template <int FINAL>
__global__ void ln_kernel(const float* __restrict__ x,
                          const float* __restrict__ g,
                          const float* __restrict__ be,
                          __half* __restrict__ outh,
                          float* __restrict__ outf) {
    int row = blockIdx.x;
    int tid = threadIdx.x;   // 128
    int lane = tid & 31, wrp = tid >> 5;
    float4 v = ((const float4*)(x + (size_t)row * Cc))[tid];

    __shared__ float ws[4];
    __shared__ float bc[2];

    float s = v.x + v.y + v.z + v.w;
#pragma unroll
    for (int o = 16; o > 0; o >>= 1) s += __shfl_xor_sync(0xffffffffu, s, o);
    if (lane == 0) ws[wrp] = s;
    __syncthreads();
    if (tid == 0) bc[0] = (ws[0] + ws[1] + ws[2] + ws[3]) * (1.f / Cc);
    __syncthreads();
    float mean = bc[0];

    float dx = v.x - mean, dy = v.y - mean, dz = v.z - mean, dw = v.w - mean;
    float vs = dx * dx + dy * dy + dz * dz + dw * dw;
#pragma unroll
    for (int o = 16; o > 0; o >>= 1) vs += __shfl_xor_sync(0xffffffffu, vs, o);
    if (lane == 0) ws[wrp] = vs;
    __syncthreads();
    if (tid == 0) bc[1] = rsqrtf((ws[0] + ws[1] + ws[2] + ws[3]) * (1.f / Cc) + 1e-5f);
    __syncthreads();
    float inv = bc[1];

    float4 gv = ((const float4*)g)[tid];
    float4 bv = ((const float4*)be)[tid];
    float o0 = dx * inv * gv.x + bv.x;
    float o1 = dy * inv * gv.y + bv.y;
    float o2 = dz * inv * gv.z + bv.z;
    float o3 = dw * inv * gv.w + bv.w;
    if (FINAL) {
        ((float4*)(outf + (size_t)row * Cc))[tid] = make_float4(o0, o1, o2, o3);
    } else {
        __half* dst = outh + (size_t)row * Cc + tid * 4;
        *(__half2*)dst       = __floats2half2_rn(o0, o1);
        *(__half2*)(dst + 2) = __floats2half2_rn(o2, o3);
    }
}

// ---------------- attention: tensor-core (mma.sync), proven R12 ------------
#define AQB 32
#define AJT 64
#define ATH 256
#define QSTW 36
#define KSTW 36
#define SCST 516
#define PSTW 260
#define SM_Q   0
#define SM_K   4608
#define SM_SC  13824
#define SM_P   79872
#define SM_INV 113152
#define SMEM_ATTN 113280

__global__ void __launch_bounds__(ATH)
attn_kernel(const __half* __restrict__ QKV, __half* __restrict__ O) {
    extern __shared__ char asmem[];
    uint32_t* qsm  = (uint32_t*)(asmem + SM_Q);
    uint32_t* ksm  = (uint32_t*)(asmem + SM_K);
    float*    sc   = (float*)(asmem + SM_SC);
    uint32_t* psm  = (uint32_t*)(asmem + SM_P);
    __half*   psmh = (__half*)psm;
    float*    invs = (float*)(asmem + SM_INV);

    int qt0 = blockIdx.x * AQB;
    int h   = blockIdx.y;
    int b   = blockIdx.z;
    int tid = threadIdx.x;
    int lane = tid & 31, wid = tid >> 5;
    int g = lane >> 2, t = lane & 3;
    int n0 = wid * 8;

    for (int i = tid; i < AQB * PSTW; i += ATH) psm[i] = 0;

    for (int i = tid; i < AQB * 16; i += ATH) {
        int r = i >> 4, dp = i & 15;
        int qq = qt0 + r;
        uint2 u = make_uint2(0u, 0u);
        if (qq < Tt) u = *(const uint2*)&QKV[(size_t)(b * Tt + qq) * QKVS + h * HD + dp * 4];
        qsm[r * QSTW + dp * 2]     = u.x;
        qsm[r * QSTW + dp * 2 + 1] = u.y;
    }
    __syncthreads();

    int qmax = min(qt0 + AQB - 1, Tt - 1);
    int ntiles = qmax / AJT + 1;

    for (int jt = 0; jt < ntiles; jt++) {
        int j0 = jt * AJT;
        for (int i = tid; i < AJT * 16; i += ATH) {
            int r = i >> 4, dp = i & 15;
            int j = j0 + r;
            uint2 u = make_uint2(0u, 0u);
            if (j < Tt) u = *(const uint2*)&QKV[(size_t)(b * Tt + j) * QKVS + Cc + h * HD + dp * 4];
            ksm[r * KSTW + dp * 2]     = u.x;
            ksm[r * KSTW + dp * 2 + 1] = u.y;
        }
        __syncthreads();

        float acc[2][4];
#pragma unroll
        for (int i = 0; i < 2; i++)
#pragma unroll
            for (int r = 0; r < 4; r++) acc[i][r] = 0.f;

#pragma unroll
        for (int ks = 0; ks < 4; ks++) {
            int kc = ks * 8;
            uint32_t bfr[2];
            bfr[0] = ksm[(n0 + g) * KSTW + kc + t];
            bfr[1] = ksm[(n0 + g) * KSTW + kc + t + 4];
#pragma unroll
            for (int i = 0; i < 2; i++) {
                int r = i * 16;
                uint32_t af[4];
                af[0] = qsm[(r + g) * QSTW + kc + t];
                af[1] = qsm[(r + g + 8) * QSTW + kc + t];
                af[2] = qsm[(r + g) * QSTW + kc + t + 4];
                af[3] = qsm[(r + g + 8) * QSTW + kc + t + 4];
                mma_f16(acc[i], af, bfr);
            }
        }
        int col = j0 + n0 + 2 * t;
#pragma unroll
        for (int i = 0; i < 2; i++) {
            int m = i * 16 + g;
            int qa = qt0 + m;
            int qb = qa + 8;
            float s0 = (col     <= qa) ? acc[i][0] * SCALE : -1e30f;
            float s1 = (col + 1 <= qa) ? acc[i][1] * SCALE : -1e30f;
            float s2 = (col     <= qb) ? acc[i][2] * SCALE : -1e30f;
            float s3 = (col + 1 <= qb) ? acc[i][3] * SCALE : -1e30f;
            *(float2*)&sc[m * SCST + col]       = make_float2(s0, s1);
            *(float2*)&sc[(m + 8) * SCST + col] = make_float2(s2, s3);
        }
        __syncthreads();
    }

    for (int rr = 0; rr < 4; rr++) {
        int m = wid * 4 + rr;
        int q = qt0 + m;
        if (q > qmax) continue;
        float* srow = sc + m * SCST;
        float mx = -1e30f;
        for (int j = lane; j <= q; j += 32) mx = fmaxf(mx, srow[j]);
#pragma unroll
        for (int o = 16; o > 0; o >>= 1) mx = fmaxf(mx, __shfl_xor_sync(0xffffffffu, mx, o));
        float sum = 0.f;
        for (int j = lane; j <= q; j += 32) {
            float e = __expf(srow[j] - mx);
            psmh[m * (PSTW * 2) + j] = __float2half(e);
            sum += e;
        }
#pragma unroll
        for (int o = 16; o > 0; o >>= 1) sum += __shfl_xor_sync(0xffffffffu, sum, o);
        if (lane == 0) invs[m] = 1.f / sum;
    }
    __syncthreads();

    float oacc[2][4];
#pragma unroll
    for (int i = 0; i < 2; i++)
#pragma unroll
        for (int r = 0; r < 4; r++) oacc[i][r] = 0.f;

    for (int jt = 0; jt < ntiles; jt++) {
        int j0 = jt * AJT;
        for (int i = tid; i < AJT * 16; i += ATH) {
            int r  = i >> 4;
            int dp = (i & 15) * 4;
            int j  = j0 + r;
            uint2 u = make_uint2(0u, 0u);
            if (j < Tt) u = *(const uint2*)&QKV[(size_t)(b * Tt + j) * QKVS + 2 * Cc + h * HD + dp];
            __half hs[4];
            *(uint2*)hs = u;
            __half* vt = (__half*)ksm;
            vt[(dp + 0) * (KSTW * 2) + r] = hs[0];
            vt[(dp + 1) * (KSTW * 2) + r] = hs[1];
            vt[(dp + 2) * (KSTW * 2) + r] = hs[2];
            vt[(dp + 3) * (KSTW * 2) + r] = hs[3];
        }
        __syncthreads();

        int pw = (j0 >> 1);
#pragma unroll
        for (int ks = 0; ks < 4; ks++) {
            int kc = ks * 8;
            uint32_t bfr[2];
            bfr[0] = ksm[(n0 + g) * KSTW + kc + t];
            bfr[1] = ksm[(n0 + g) * KSTW + kc + t + 4];
#pragma unroll
            for (int i = 0; i < 2; i++) {
                int r = i * 16;
                uint32_t af[4];
                af[0] = psm[(r + g) * PSTW + pw + kc + t];
                af[1] = psm[(r + g + 8) * PSTW + pw + kc + t];
                af[2] = psm[(r + g) * PSTW + pw + kc + t + 4];
                af[3] = psm[(r + g + 8) * PSTW + pw + kc + t + 4];
                mma_f16(oacc[i], af, bfr);
            }
        }
        __syncthreads();
    }

#pragma unroll
    for (int i = 0; i < 2; i++) {
        int m = i * 16 + g;
        int qa = qt0 + m;
        if (qa < Tt) {
            float iv = invs[m];
            *(__half2*)&O[(size_t)(b * Tt + qa) * Cc + h * HD + n0 + 2 * t] =
                __floats2half2_rn(oacc[i][0] * iv, oacc[i][1] * iv);
        }
        int qb = qa + 8;
        if (qb < Tt) {
            float iv = invs[m + 8];
            *(__half2*)&O[(size_t)(b * Tt + qb) * Cc + h * HD + n0 + 2 * t] =
                __floats2half2_rn(oacc[i][2] * iv, oacc[i][3] * iv);
        }
    }
}

// ---------------- host orchestration ---------------------------------------
extern "C" void kernel_launch(void* const* d_in, const int* in_sizes, int n_in,
                              void* d_out, int out_size) {
    (void)in_sizes; (void)n_in; (void)out_size;
    const float* x     = (const float*)d_in[0];
    const float* dw_w  = (const float*)d_in[1];
    const float* dw_b  = (const float*)d_in[2];
    const float* pw_w  = (const float*)d_in[3];
    const float* pw_b  = (const float*)d_in[4];
    const float* cln_g = (const float*)d_in[5];
    const float* cln_b = (const float*)d_in[6];
    const float* wq    = (const float*)d_in[7];
    const float* bq    = (const float*)d_in[8];
    const float* wk    = (const float*)d_in[9];
    const float* bk    = (const float*)d_in[10];
    const float* wv    = (const float*)d_in[11];
    const float* bv    = (const float*)d_in[12];
    const float* wo    = (const float*)d_in[13];
    const float* bo    = (const float*)d_in[14];
    const float* aln_g = (const float*)d_in[15];
    const float* aln_b = (const float*)d_in[16];
    const float* w1    = (const float*)d_in[17];
    const float* b1    = (const float*)d_in[18];
    const float* w2    = (const float*)d_in[19];
    const float* b2    = (const float*)d_in[20];
    const float* fln_g = (const float*)d_in[21];
    const float* fln_b = (const float*)d_in[22];
    float* out = (float*)d_out;

    __half *hA, *hB, *hH, *pwh, *qkvh, *woh, *w1h, *w2h;
    float *f32buf, *bqkv;
    cudaGetSymbolAddress((void**)&hA,   g_hA);
    cudaGetSymbolAddress((void**)&hB,   g_hB);
    cudaGetSymbolAddress((void**)&hH,   g_hH);
    cudaGetSymbolAddress((void**)&f32buf, g_f);
    cudaGetSymbolAddress((void**)&pwh,  g_pwh);
    cudaGetSymbolAddress((void**)&qkvh, g_qkvh);
    cudaGetSymbolAddress((void**)&bqkv, g_bqkv);
    cudaGetSymbolAddress((void**)&woh,  g_woh);
    cudaGetSymbolAddress((void**)&w1h,  g_w1h);
    cudaGetSymbolAddress((void**)&w2h,  g_w2h);

    cudaFuncSetAttribute(gemm_f16<0, 0>, cudaFuncAttributeMaxDynamicSharedMemorySize, SMEM_GEMM);
    cudaFuncSetAttribute(gemm_f16<0, 1>, cudaFuncAttributeMaxDynamicSharedMemorySize, SMEM_GEMM);
    cudaFuncSetAttribute(gemm_f16<1, 1>, cudaFuncAttributeMaxDynamicSharedMemorySize, SMEM_GEMM);
    cudaFuncSetAttribute(attn_kernel, cudaFuncAttributeMaxDynamicSharedMemorySize, SMEM_ATTN);

    dim3 gN512(Cc / GBN, MT / GBM);      // (2, 63)
    dim3 gN1536(QKVS / GBN, MT / GBM);   // (6, 63)
    dim3 gN2048(HIDd / GBN, MT / GBM);   // (8, 63)
    dim3 attnGrid((Tt + AQB - 1) / AQB, NHh, Bz);
    int dwBlocks = (BT / 4);             // (BT/4)*256 threads / 256

    prep_weights<<<(NPREP1 + 255) / 256, 256>>>(pw_w, wq, wk, wv, wo, w1, w2);
    prep_bias<<<(NQB_ + 255) / 256, 256>>>(bq, bk, bv);

    const float* cur = x;
    for (int l = 0; l < Ll; l++) {
        // ---- conv block 0 ----
        dwconv_kernel<float><<<dwBlocks, 256>>>(cur,
            dw_w + (size_t)(l * NCb + 0) * Cc * Kk, dw_b + (size_t)(l * NCb + 0) * Cc, hA);
        gemm_f16<0, 0><<<gN512, 512, SMEM_GEMM>>>(hA, pwh + (size_t)(l * NCb + 0) * Cc * Cc,
            pw_b + (size_t)(l * NCb + 0) * Cc, f32buf, Cc, Cc);
        ln_kernel<0><<<BT, 128>>>(f32buf, cln_g + (size_t)(l * NCb + 0) * Cc,
            cln_b + (size_t)(l * NCb + 0) * Cc, hB, nullptr);

        // ---- conv block 1 ----
        dwconv_kernel<__half><<<dwBlocks, 256>>>(hB,
            dw_w + (size_t)(l * NCb + 1) * Cc * Kk, dw_b + (size_t)(l * NCb + 1) * Cc, hA);
        gemm_f16<0, 0><<<gN512, 512, SMEM_GEMM>>>(hA, pwh + (size_t)(l * NCb + 1) * Cc * Cc,
            pw_b + (size_t)(l * NCb + 1) * Cc, f32buf, Cc, Cc);
        ln_kernel<0><<<BT, 128>>>(f32buf, cln_g + (size_t)(l * NCb + 1) * Cc,
            cln_b + (size_t)(l * NCb + 1) * Cc, hB, nullptr);

        // ---- attention ----
        gemm_f16<0, 1><<<gN1536, 512, SMEM_GEMM>>>(hB, qkvh + (size_t)l * QKVS * Cc,
            bqkv + (size_t)l * QKVS, hH, QKVS, Cc);
        attn_kernel<<<attnGrid, ATH, SMEM_ATTN>>>(hH, hA);
        gemm_f16<0, 0><<<gN512, 512, SMEM_GEMM>>>(hA, woh + (size_t)l * Cc * Cc,
            bo + (size_t)l * Cc, f32buf, Cc, Cc);
        ln_kernel<0><<<BT, 128>>>(f32buf, aln_g + (size_t)l * Cc, aln_b + (size_t)l * Cc, hB, nullptr);

        // ---- FFN ----
        gemm_f16<1, 1><<<gN2048, 512, SMEM_GEMM>>>(hB, w1h + (size_t)l * HIDd * Cc,
            b1 + (size_t)l * HIDd, hH, HIDd, Cc);
        gemm_f16<0, 0><<<gN512, 512, SMEM_GEMM>>>(hH, w2h + (size_t)l * Cc * HIDd,
            b2 + (size_t)l * Cc, f32buf, Cc, HIDd);

        float* Y = out + (size_t)l * BT * Cc;
        ln_kernel<1><<<BT, 128>>>(f32buf, fln_g + (size_t)l * Cc, fln_b + (size_t)l * Cc, nullptr, Y);
        cur = Y;
    }
}